// round 13
// baseline (speedup 1.0000x reference)
#include <cuda_runtime.h>
#include <cuda_bf16.h>

#define HIDDEN 4096
#define TOKENS 16384
#define TP 4
#define EPS 1e-6f

#define THREADS 512
#define V4_PER_ROW (HIDDEN / 4)              // 1024 float4 per row
#define V4_PER_THREAD (V4_PER_ROW / THREADS) // 2
#define NWARPS (THREADS / 32)                // 16

__global__ __launch_bounds__(THREADS)
void allreduce_rmsnorm_kernel(const float4* __restrict__ hs,
                              const float4* __restrict__ w,
                              float4* __restrict__ out) {
    const int token = blockIdx.x;
    const size_t row = (size_t)token * V4_PER_ROW;
    const size_t tp_stride = (size_t)TOKENS * V4_PER_ROW;

    float4 acc[V4_PER_THREAD];
    float ss = 0.0f;

    // Load + tp-reduce. 8 independent fully-coalesced loads per thread.
    #pragma unroll
    for (int j = 0; j < V4_PER_THREAD; j++) {
        const int col = threadIdx.x + j * THREADS;
        float4 v = hs[row + col];
        #pragma unroll
        for (int t = 1; t < TP; t++) {
            const float4 u = hs[(size_t)t * tp_stride + row + col];
            v.x += u.x; v.y += u.y; v.z += u.z; v.w += u.w;
        }
        acc[j] = v;
        ss += v.x * v.x + v.y * v.y + v.z * v.z + v.w * v.w;
    }

    // Warp-level reduction of sum-of-squares.
    #pragma unroll
    for (int off = 16; off > 0; off >>= 1)
        ss += __shfl_xor_sync(0xFFFFFFFFu, ss, off);

    // Single-barrier block reduction: each warp publishes its partial, then
    // EVERY warp reduces all 16 partials itself (no 2nd barrier, no broadcast
    // dependency on warp 0). Lanes 16..31 mirror lanes 0..15 so the
    // {8,4,2,1} butterfly (which never crosses the lane-16 boundary) yields
    // the full block sum in every lane.
    __shared__ float warp_ss[NWARPS];
    const int lane = threadIdx.x & 31;
    const int wid  = threadIdx.x >> 5;
    if (lane == 0) warp_ss[wid] = ss;
    __syncthreads();

    float s = warp_ss[lane & (NWARPS - 1)];
    #pragma unroll
    for (int off = NWARPS / 2; off > 0; off >>= 1)
        s += __shfl_xor_sync(0xFFFFFFFFu, s, off);
    const float inv_rms = rsqrtf(s * (1.0f / (float)HIDDEN) + EPS);

    #pragma unroll
    for (int j = 0; j < V4_PER_THREAD; j++) {
        const int col = threadIdx.x + j * THREADS;
        const float4 g = __ldg(&w[col]);
        float4 v = acc[j];
        v.x = v.x * inv_rms * g.x;
        v.y = v.y * inv_rms * g.y;
        v.z = v.z * inv_rms * g.z;
        v.w = v.w * inv_rms * g.w;
        out[row + col] = v;
    }
}

extern "C" void kernel_launch(void* const* d_in, const int* in_sizes, int n_in,
                              void* d_out, int out_size) {
    const float4* hs = (const float4*)d_in[0];  // [tp, tokens, hidden] fp32
    // d_in[1] = residual -- unused by the reference computation
    const float4* w  = (const float4*)d_in[2];  // [hidden] fp32
    float4* out = (float4*)d_out;               // [tokens, hidden] fp32

    allreduce_rmsnorm_kernel<<<TOKENS, THREADS>>>(hs, w, out);
}

// round 14
// speedup vs baseline: 1.0099x; 1.0099x over previous
#include <cuda_runtime.h>
#include <cuda_bf16.h>

#define HIDDEN 4096
#define TOKENS 16384
#define TP 4
#define EPS 1e-6f

#define THREADS 1024
#define V4_PER_ROW (HIDDEN / 4)              // 1024 float4 per row -> 1 per thread
#define NWARPS (THREADS / 32)                // 32

__global__ __launch_bounds__(THREADS)
void allreduce_rmsnorm_kernel(const float4* __restrict__ hs,
                              const float4* __restrict__ w,
                              float4* __restrict__ out) {
    const int token = blockIdx.x;
    const size_t idx = (size_t)token * V4_PER_ROW + threadIdx.x;
    const size_t tp_stride = (size_t)TOKENS * V4_PER_ROW;

    // 4 front-batched, fully-independent coalesced loads (one per tp rank).
    const float4 r0 = hs[idx];
    const float4 r1 = hs[idx + tp_stride];
    const float4 r2 = hs[idx + 2 * tp_stride];
    const float4 r3 = hs[idx + 3 * tp_stride];

    float4 v;
    v.x = (r0.x + r1.x) + (r2.x + r3.x);
    v.y = (r0.y + r1.y) + (r2.y + r3.y);
    v.z = (r0.z + r1.z) + (r2.z + r3.z);
    v.w = (r0.w + r1.w) + (r2.w + r3.w);

    float ss = v.x * v.x + v.y * v.y + v.z * v.z + v.w * v.w;

    // Warp-level reduction of sum-of-squares.
    #pragma unroll
    for (int off = 16; off > 0; off >>= 1)
        ss += __shfl_xor_sync(0xFFFFFFFFu, ss, off);

    // Single-barrier block reduction: 32 warp partials; every warp loads all
    // 32 and butterflies over {16,8,4,2,1} -> full block sum in every lane.
    __shared__ float warp_ss[NWARPS];
    const int lane = threadIdx.x & 31;
    const int wid  = threadIdx.x >> 5;
    if (lane == 0) warp_ss[wid] = ss;
    __syncthreads();

    float s = warp_ss[lane];
    #pragma unroll
    for (int off = 16; off > 0; off >>= 1)
        s += __shfl_xor_sync(0xFFFFFFFFu, s, off);
    const float inv_rms = rsqrtf(s * (1.0f / (float)HIDDEN) + EPS);

    const float4 g = __ldg(&w[threadIdx.x]);
    v.x = v.x * inv_rms * g.x;
    v.y = v.y * inv_rms * g.y;
    v.z = v.z * inv_rms * g.z;
    v.w = v.w * inv_rms * g.w;
    out[idx] = v;
}

extern "C" void kernel_launch(void* const* d_in, const int* in_sizes, int n_in,
                              void* d_out, int out_size) {
    const float4* hs = (const float4*)d_in[0];  // [tp, tokens, hidden] fp32
    // d_in[1] = residual -- unused by the reference computation
    const float4* w  = (const float4*)d_in[2];  // [hidden] fp32
    float4* out = (float4*)d_out;               // [tokens, hidden] fp32

    allreduce_rmsnorm_kernel<<<TOKENS, THREADS>>>(hs, w, out);
}